// round 6
// baseline (speedup 1.0000x reference)
#include <cuda_runtime.h>
#include <math.h>

#define T_SEQ 700
#define BATCH 32
#define HID 800
#define DIN 53
#define G4 3200       // 4*HID
#define L1K 1600      // 2*HID
#define NA 60
#define RNNOUT 1653   // 2*HID + DIN
#define NB_LSTM 148
#define HSTR 804      // padded h stride (floats): 16B-aligned, conflict-free LDS.128 phases
// smem floats: hs 32*804 + wsm 32*800 + pre 44*32 + csm 11*32
#define LSTM_SMEM ((32*HSTR + 32*HID + 44*BATCH + 11*BATCH) * 4)

// ---------------- scratch (static device allocations) ----------------
__device__ float g_xT  [(size_t)T_SEQ*DIN*BATCH];      // x transposed  [t][53][32]
__device__ float g_cbuf[(size_t)T_SEQ*BATCH*G4];       // GEMM output   [t*32+b][3200]
__device__ float g_xgTf[(size_t)T_SEQ*G4*BATCH];       // xg fwd        [t][3200][32]
__device__ float g_xgTb[(size_t)T_SEQ*G4*BATCH];       // xg bwd        [t][3200][32]
__device__ float g_h0T [(size_t)T_SEQ*L1K*BATCH];      // layer0 out    [t][1600][32]
__device__ float g_h1T [(size_t)T_SEQ*L1K*BATCH];      // layer1 out    [t][1600][32]
__device__ float g_hstate[2*2*HID*BATCH];              // [dir][parity][b][800]
__device__ float g_dih [T_SEQ*BATCH*3];
__device__ unsigned g_bar_cnt;
__device__ volatile unsigned g_bar_gen;

// ---------------- f32x2 packed helpers --------------------------------------
__device__ __forceinline__ void ffma2(unsigned long long& d,
                                      unsigned long long a, unsigned long long b) {
    asm("fma.rn.f32x2 %0, %1, %2, %0;" : "+l"(d) : "l"(a), "l"(b));
}
__device__ __forceinline__ unsigned long long pack2(float lo, float hi) {
    unsigned long long r;
    asm("mov.b64 %0, {%1,%2};" : "=l"(r) : "f"(lo), "f"(hi));
    return r;
}
__device__ __forceinline__ unsigned long long dup2(float v) {
    unsigned long long r;
    asm("mov.b64 %0, {%1,%1};" : "=l"(r) : "f"(v));
    return r;
}
__device__ __forceinline__ float2 unpack2(unsigned long long v) {
    float2 r;
    asm("mov.b64 {%0,%1}, %2;" : "=f"(r.x), "=f"(r.y) : "l"(v));
    return r;
}

// ---------------- cp.async helpers ------------------------------------------
__device__ __forceinline__ void cp_async4(void* smem_dst, const void* gsrc) {
    unsigned s = (unsigned)__cvta_generic_to_shared(smem_dst);
    asm volatile("cp.async.ca.shared.global [%0], [%1], 4;" :: "r"(s), "l"(gsrc));
}
__device__ __forceinline__ void cp_commit() {
    asm volatile("cp.async.commit_group;");
}
template<int N> __device__ __forceinline__ void cp_wait() {
    asm volatile("cp.async.wait_group %0;" :: "n"(N));
}

// ---------------- build x (embedding + evolutionary concat), TKB layout ----
__global__ __launch_bounds__(256) void build_x_kernel(
        const int* __restrict__ primary,
        const float* __restrict__ evo,
        const float* __restrict__ emb) {
    int t = blockIdx.x;
    for (int idx = threadIdx.x; idx < DIN*BATCH; idx += 256) {
        int d = idx >> 5;
        int b = idx & 31;
        float v;
        if (d < 32) {
            int p = primary[t*BATCH + b];
            v = emb[p*32 + d];
        } else {
            v = evo[((size_t)t*BATCH + b)*21 + (d - 32)];
        }
        g_xT[((size_t)t*DIN + d)*BATCH + b] = v;
    }
}

// ---------------- fp32x2 SGEMM: cbuf[M][3200] = A_tkb @ B^T + bias ----------
// A in TKB layout [T][K][32] (logical row m = t*32+b), B row-major [3200][K]
// 3-stage cp.async pipeline, packed f32x2 FMA in the 8x8 register tile.
__global__ __launch_bounds__(256, 2) void gemm_tkb_kernel(
        const float* __restrict__ Bm, const float* __restrict__ bias,
        int K, int a_sel) {
    const float* __restrict__ A = a_sel ? g_h0T : g_xT;
    __shared__ float As[3][8][128];
    __shared__ float Bs[3][8][128];
    int m0 = blockIdx.x * 128;
    int n0 = blockIdx.y * 128;
    int tid = threadIdx.x;
    int tx = tid & 15, ty = tid >> 4;
    int klA = tid >> 5, blA = tid & 31;
    int klB = tid & 7,  nlB = tid >> 3;
    int nt = (K + 7) / 8;

    auto issue = [&](int kt, int buf) {
        int kb = kt * 8;
        #pragma unroll
        for (int i = 0; i < 4; i++) {
            int m = m0 + blA + i*32;
            int k = kb + klA;
            float* dst = &As[buf][klA][blA + i*32];
            if (k < K) {
                int tt = m >> 5, bb = m & 31;
                cp_async4(dst, &A[((size_t)tt*K + k)*BATCH + bb]);
            } else *dst = 0.f;
        }
        #pragma unroll
        for (int i = 0; i < 4; i++) {
            int n = n0 + nlB + i*32;
            int k = kb + klB;
            float* dst = &Bs[buf][klB][nlB + i*32];
            if (k < K) cp_async4(dst, &Bm[(size_t)n*K + k]);
            else *dst = 0.f;
        }
        cp_commit();
    };

    unsigned long long acc2[8][4];
    #pragma unroll
    for (int i = 0; i < 8; i++)
        #pragma unroll
        for (int j = 0; j < 4; j++) acc2[i][j] = 0ULL;

    issue(0, 0);
    if (nt > 1) issue(1, 1);

    for (int kt = 0; kt < nt; kt++) {
        if (kt < nt - 1) cp_wait<1>(); else cp_wait<0>();
        __syncthreads();
        if (kt + 2 < nt) issue(kt + 2, (kt + 2) % 3);
        int cb = kt % 3;
        #pragma unroll
        for (int kk = 0; kk < 8; kk++) {
            float4 a0 = *(const float4*)&As[cb][kk][ty*8];
            float4 a1 = *(const float4*)&As[cb][kk][ty*8 + 4];
            ulonglong2 bp0 = *(const ulonglong2*)&Bs[cb][kk][tx*8];
            ulonglong2 bp1 = *(const ulonglong2*)&Bs[cb][kk][tx*8 + 4];
            unsigned long long ad[8];
            ad[0] = dup2(a0.x); ad[1] = dup2(a0.y);
            ad[2] = dup2(a0.z); ad[3] = dup2(a0.w);
            ad[4] = dup2(a1.x); ad[5] = dup2(a1.y);
            ad[6] = dup2(a1.z); ad[7] = dup2(a1.w);
            #pragma unroll
            for (int i = 0; i < 8; i++) {
                ffma2(acc2[i][0], ad[i], bp0.x);
                ffma2(acc2[i][1], ad[i], bp0.y);
                ffma2(acc2[i][2], ad[i], bp1.x);
                ffma2(acc2[i][3], ad[i], bp1.y);
            }
        }
    }

    #pragma unroll
    for (int i = 0; i < 8; i++) {
        int row = m0 + ty*8 + i;
        float* crow = &g_cbuf[(size_t)row*G4 + n0 + tx*8];
        #pragma unroll
        for (int j2 = 0; j2 < 4; j2++) {
            float2 v = unpack2(acc2[i][j2]);
            int col = n0 + tx*8 + 2*j2;
            crow[2*j2 + 0] = v.x + __ldg(&bias[col + 0]);
            crow[2*j2 + 1] = v.y + __ldg(&bias[col + 1]);
        }
    }
}

// ---------------- transpose g_cbuf [t*32+b][3200] -> xgT [t][3200][32] ------
__global__ void transpose_kernel(int dst_sel) {
    float* __restrict__ dst = dst_sel ? g_xgTb : g_xgTf;
    __shared__ float sm[32][33];
    int t  = blockIdx.x;
    int n0 = blockIdx.y * 32;
    int x = threadIdx.x, y = threadIdx.y;   // 32 x 8
    #pragma unroll
    for (int i = 0; i < 4; i++) {
        int b = y + i*8;
        sm[b][x] = g_cbuf[((size_t)t*BATCH + b)*G4 + n0 + x];
    }
    __syncthreads();
    #pragma unroll
    for (int i = 0; i < 4; i++) {
        int n = y + i*8;
        dst[((size_t)t*G4 + n0 + n)*BATCH + x] = sm[x][n];
    }
}

// ---------------- device-wide barrier (generation based) --------------------
__device__ __forceinline__ void grid_barrier() {
    __syncthreads();
    if (threadIdx.x == 0) {
        unsigned my = g_bar_gen;
        __threadfence();
        if (atomicAdd(&g_bar_cnt, 1) == NB_LSTM - 1) {
            g_bar_cnt = 0;
            __threadfence();
            g_bar_gen = my + 1;
        } else {
            while (g_bar_gen == my) { }
            __threadfence();
        }
    }
    __syncthreads();
}

// ---------------- persistent bidirectional LSTM layer -----------------------
// 148 blocks: 74 per direction. Block owns nh (10-11) hidden units = 4*nh gate
// rows. Each warp sweeps up to 6 rows per k-pass (rows w+8s). Rows 0..31 of the
// block's gate rows have their Whh rows cached in smem (warp-uniform broadcast
// loads); rows 32..47 stream from L2. Inner product uses packed fma.rn.f32x2
// with the k-pair packed: h stored [b][k] so LDS.128 gives natural f32x2 pairs,
// and row-major Whh float4s are natural f32x2 pairs.
__global__ __launch_bounds__(256, 1) void lstm_kernel(
        const float* __restrict__ Whhf, const float* __restrict__ Whhb,
        int layer) {
    extern __shared__ float smem[];
    float* hs  = smem;                        // [32][HSTR] prev h, [b][k]
    float* wsm = hs + 32*HSTR;                // [32][800] cached Whh rows
    float* pre = wsm + 32*HID;                // [44*32] gate pre-activations
    float* csm = pre + 44*BATCH;              // [11*32] cell state
    float* hout = layer ? g_h1T : g_h0T;

    int bid = blockIdx.x;
    int dir = (bid >= 74) ? 1 : 0;
    int lb  = dir ? bid - 74 : bid;           // 0..73
    int nh, h0;
    if (lb < 60) { nh = 11; h0 = lb*11; }
    else         { nh = 10; h0 = 660 + (lb-60)*10; }
    const float* __restrict__ xgT = dir ? g_xgTb : g_xgTf;
    const float* __restrict__ Whh = dir ? Whhb : Whhf;

    int tid = threadIdx.x;
    int lane = tid & 31, w = tid >> 5;
    int nrows = nh * 4;                       // 40 or 44

    int grows[6];
    bool valid[6];
    #pragma unroll
    for (int s = 0; s < 6; s++) {
        int lr = w + 8*s;
        bool v = lr < nrows;
        int lru = v ? lr : 0;
        grows[s] = (lru & 3)*HID + h0 + (lru >> 2);
        valid[s] = v;
    }
    const float* wq0 = Whh + (size_t)grows[4]*HID;   // streamed rows (s=4,5)
    const float* wq1 = Whh + (size_t)grows[5]*HID;

    // preload cached weight rows lr = 0..31 (always valid: nrows >= 40)
    for (int lr = 0; lr < 32; lr++) {
        int g = (lr & 3)*HID + h0 + (lr >> 2);
        const float* src = Whh + (size_t)g*HID;
        for (int k = tid; k < HID; k += 256) wsm[lr*HID + k] = src[k];
    }

    // zero-init c (smem) and own slots of h parity-0 buffer [b][k]
    for (int i = tid; i < nh*BATCH; i += 256) {
        csm[i] = 0.f;
        int hl = i >> 5, b = i & 31;
        g_hstate[(size_t)(dir*2 + 0)*HID*BATCH + b*HID + (h0 + hl)] = 0.f;
    }
    grid_barrier();

    for (int t = 0; t < T_SEQ; t++) {
        int te = dir ? (T_SEQ - 1 - t) : t;
        int p = t & 1;
        // stage previous h [b][k] into smem (coalesced LDG, conflict-free STS)
        const float* hsg = &g_hstate[(size_t)(dir*2 + p)*HID*BATCH];
        for (int i = tid; i < HID*BATCH; i += 256) {
            int b = i / HID, k = i - b*HID;
            hs[b*HSTR + k] = __ldcg(&hsg[i]);
        }
        __syncthreads();

        // phase A: gate pre-activations, 6 rows per warp, packed f32x2
        unsigned long long a0[6], a1[6];
        #pragma unroll
        for (int s = 0; s < 6; s++) {
            float xg = xgT[((size_t)te*G4 + grows[s])*BATCH + lane];
            a0[s] = pack2(xg, 0.f);
            a1[s] = 0ULL;
        }
        const float* hrow = &hs[lane*HSTR];
        #pragma unroll 4
        for (int k = 0; k < HID; k += 4) {
            ulonglong2 hv = *(const ulonglong2*)(hrow + k);
            #pragma unroll
            for (int s = 0; s < 4; s++) {
                ulonglong2 wv = *(const ulonglong2*)&wsm[(w + 8*s)*HID + k];
                ffma2(a0[s], hv.x, wv.x);
                ffma2(a1[s], hv.y, wv.y);
            }
            {
                ulonglong2 wv = *(const ulonglong2*)(wq0 + k);
                ffma2(a0[4], hv.x, wv.x);
                ffma2(a1[4], hv.y, wv.y);
            }
            {
                ulonglong2 wv = *(const ulonglong2*)(wq1 + k);
                ffma2(a0[5], hv.x, wv.x);
                ffma2(a1[5], hv.y, wv.y);
            }
        }
        #pragma unroll
        for (int s = 0; s < 6; s++) {
            if (valid[s]) {
                float2 x = unpack2(a0[s]);
                float2 y = unpack2(a1[s]);
                pre[(w + 8*s)*BATCH + lane] = (x.x + x.y) + (y.x + y.y);
            }
        }
        __syncthreads();

        // phase B: gate nonlinearity + state update
        for (int i = tid; i < nh*BATCH; i += 256) {
            int hl = i >> 5, b = i & 31;
            float iv = pre[(hl*4+0)*BATCH + b];
            float fv = pre[(hl*4+1)*BATCH + b];
            float gv = pre[(hl*4+2)*BATCH + b];
            float ov = pre[(hl*4+3)*BATCH + b];
            float si = 1.f/(1.f + expf(-iv));
            float sf = 1.f/(1.f + expf(-fv));
            float so = 1.f/(1.f + expf(-ov));
            float c  = sf*csm[i] + si*tanhf(gv);
            float hv = so*tanhf(c);
            csm[i] = c;
            int hi = h0 + hl;
            g_hstate[(size_t)(dir*2 + (1-p))*HID*BATCH + b*HID + hi] = hv;
            hout[((size_t)te*L1K + dir*HID + hi)*BATCH + b] = hv;
        }
        grid_barrier();
    }
}

// ---------------- FC + softmax-free angularization -> dihedrals -------------
__global__ __launch_bounds__(256) void fc_dih_kernel(
        const float* __restrict__ fcW, const float* __restrict__ fcb,
        const float* __restrict__ alphabet) {
    __shared__ float chunk[256*BATCH];   // 32KB feature chunk [k][b]
    __shared__ float lsm[NA*BATCH];
    __shared__ float sn[NA*3], cs[NA*3];
    int t = blockIdx.x;
    int tid = threadIdx.x;
    int lane = tid & 31, w = tid >> 5;

    float acc[8];
    #pragma unroll
    for (int i = 0; i < 8; i++) acc[i] = 0.f;

    for (int c0 = 0; c0 < RNNOUT; c0 += 256) {
        int clen = RNNOUT - c0; if (clen > 256) clen = 256;
        for (int idx = tid; idx < clen*BATCH; idx += 256) {
            int k = idx >> 5, b = idx & 31;
            int f = c0 + k;
            chunk[idx] = (f < L1K)
                ? g_h1T[((size_t)t*L1K + f)*BATCH + b]
                : g_xT [((size_t)t*DIN + (f - L1K))*BATCH + b];
        }
        __syncthreads();
        #pragma unroll
        for (int i = 0; i < 8; i++) {
            int a = w*8 + i;
            if (a < NA) {
                const float* wr = fcW + (size_t)a*RNNOUT + c0;
                float s = acc[i];
                #pragma unroll 4
                for (int k = 0; k < clen; k++)
                    s = fmaf(__ldg(wr + k), chunk[k*BATCH + lane], s);
                acc[i] = s;
            }
        }
        __syncthreads();
    }
    #pragma unroll
    for (int i = 0; i < 8; i++) {
        int a = w*8 + i;
        if (a < NA) lsm[a*BATCH + lane] = acc[i] + fcb[a];
    }
    for (int i = tid; i < NA*3; i += 256) {
        float v = alphabet[i];
        sn[i] = sinf(v); cs[i] = cosf(v);
    }
    __syncthreads();
    if (tid < 96) {
        int b = tid & 31, j = tid >> 5;
        float ss = 0.f, cc = 0.f;
        for (int a = 0; a < NA; a++) {
            float e = expf(lsm[a*BATCH + b]);   // softmax Z cancels in atan2
            ss = fmaf(e, sn[a*3 + j], ss);
            cc = fmaf(e, cs[a*3 + j], cc);
        }
        g_dih[((size_t)t*BATCH + b)*3 + j] = atan2f(ss, cc);
    }
}

// ---------------- dihedral -> points -> NeRF coordinate extension -----------
__global__ void geometry_kernel(float* __restrict__ out) {
    int b = threadIdx.x;   // 0..31, one lane per batch element
    const float PI = 3.14159265358979323846f;
    float BL[3] = {145.801f, 152.326f, 132.868f};
    float BA[3] = {2.124f, 1.941f, 2.028f};
    float rct[3], rst[3];
    #pragma unroll
    for (int j = 0; j < 3; j++) {
        rct[j] = BL[j]*cosf(PI - BA[j]);
        rst[j] = BL[j]*sinf(PI - BA[j]);
    }
    float ax = -sqrtf(0.5f), ay = sqrtf(1.5f), az = 0.f;
    float bx = -sqrtf(2.0f), by = 0.f,        bz = 0.f;
    float cx = 0.f, cy = 0.f, cz = 0.f;

    for (int i = 0; i < 3*T_SEQ; i++) {
        int t = i / 3, j = i - 3*t;
        float d  = g_dih[((size_t)t*BATCH + b)*3 + j];
        float p0 = rct[j];
        float p1 = cosf(d)*rst[j];
        float p2 = sinf(d)*rst[j];

        float ux = cx-bx, uy = cy-by, uz = cz-bz;
        float inv = 1.f/sqrtf(ux*ux + uy*uy + uz*uz + 1e-12f);
        float bcx = ux*inv, bcy = uy*inv, bcz = uz*inv;

        float vx = bx-ax, vy = by-ay, vz = bz-az;
        float nx0 = vy*bcz - vz*bcy;
        float ny0 = vz*bcx - vx*bcz;
        float nz0 = vx*bcy - vy*bcx;
        float inv2 = 1.f/sqrtf(nx0*nx0 + ny0*ny0 + nz0*nz0 + 1e-12f);
        float nx = nx0*inv2, ny = ny0*inv2, nz = nz0*inv2;

        float mx = ny*bcz - nz*bcy;
        float my = nz*bcx - nx*bcz;
        float mz = nx*bcy - ny*bcx;

        float ox = cx + p0*bcx + p1*mx + p2*nx;
        float oy = cy + p0*bcy + p1*my + p2*ny;
        float oz = cz + p0*bcz + p1*mz + p2*nz;

        size_t o = ((size_t)i*BATCH + b)*3;
        out[o+0] = ox; out[o+1] = oy; out[o+2] = oz;

        ax = bx; ay = by; az = bz;
        bx = cx; by = cy; bz = cz;
        cx = ox; cy = oy; cz = oz;
    }
}

// ---------------- launch ----------------------------------------------------
extern "C" void kernel_launch(void* const* d_in, const int* in_sizes, int n_in,
                              void* d_out, int out_size) {
    const int*   primary = (const int*)  d_in[0];
    const float* evo     = (const float*)d_in[1];
    // d_in[2] = seq_length (fixed 700, ignored)
    const float* emb     = (const float*)d_in[3];
    const float* Wih0f   = (const float*)d_in[4];
    const float* Whh0f   = (const float*)d_in[5];
    const float* b0f     = (const float*)d_in[6];
    const float* Wih0b   = (const float*)d_in[7];
    const float* Whh0b   = (const float*)d_in[8];
    const float* b0b     = (const float*)d_in[9];
    const float* Wih1f   = (const float*)d_in[10];
    const float* Whh1f   = (const float*)d_in[11];
    const float* b1f     = (const float*)d_in[12];
    const float* Wih1b   = (const float*)d_in[13];
    const float* Whh1b   = (const float*)d_in[14];
    const float* b1b     = (const float*)d_in[15];
    const float* fcW     = (const float*)d_in[16];
    const float* fcb     = (const float*)d_in[17];
    const float* alphabet= (const float*)d_in[18];
    float* out = (float*)d_out;

    cudaFuncSetAttribute(lstm_kernel,
                         cudaFuncAttributeMaxDynamicSharedMemorySize, LSTM_SMEM);

    dim3 ggrid(175, 25);           // 22400/128, 3200/128
    dim3 tgrid(T_SEQ, 100);        // 3200/32
    dim3 tblk(32, 8);

    build_x_kernel<<<T_SEQ, 256>>>(primary, evo, emb);

    // layer 0 input projections
    gemm_tkb_kernel<<<ggrid, 256>>>(Wih0f, b0f, DIN, 0);
    transpose_kernel<<<tgrid, tblk>>>(0);
    gemm_tkb_kernel<<<ggrid, 256>>>(Wih0b, b0b, DIN, 0);
    transpose_kernel<<<tgrid, tblk>>>(1);
    lstm_kernel<<<NB_LSTM, 256, LSTM_SMEM>>>(Whh0f, Whh0b, 0);

    // layer 1 input projections
    gemm_tkb_kernel<<<ggrid, 256>>>(Wih1f, b1f, L1K, 1);
    transpose_kernel<<<tgrid, tblk>>>(0);
    gemm_tkb_kernel<<<ggrid, 256>>>(Wih1b, b1b, L1K, 1);
    transpose_kernel<<<tgrid, tblk>>>(1);
    lstm_kernel<<<NB_LSTM, 256, LSTM_SMEM>>>(Whh1f, Whh1b, 1);

    fc_dih_kernel<<<T_SEQ, 256>>>(fcW, fcb, alphabet);
    geometry_kernel<<<1, 32>>>(out);
}

// round 13
// speedup vs baseline: 1.6858x; 1.6858x over previous
#include <cuda_runtime.h>
#include <math.h>

#define T_SEQ 700
#define BATCH 32
#define HID 800
#define DIN 53
#define G4 3200       // 4*HID
#define L1K 1600      // 2*HID
#define NA 60
#define RNNOUT 1653   // 2*HID + DIN
#define NB_LSTM 148
#define HSTR 804      // padded h stride (floats): 16B-aligned, conflict-free LDS.128 phases
#define GP 132        // GEMM smem row pad (floats): 16B-aligned, kills STS/LDS conflicts
// smem floats: hs 32*804 + wsm 32*800 + pre 44*32 + csm 11*32
#define LSTM_SMEM ((32*HSTR + 32*HID + 44*BATCH + 11*BATCH) * 4)

// ---------------- scratch (static device allocations) ----------------
__device__ float g_xT  [(size_t)T_SEQ*DIN*BATCH];      // x transposed  [t][53][32]
__device__ float g_cbuf[(size_t)T_SEQ*BATCH*G4];       // GEMM output   [t*32+b][3200]
__device__ float g_xgTf[(size_t)T_SEQ*G4*BATCH];       // xg fwd        [t][3200][32]
__device__ float g_xgTb[(size_t)T_SEQ*G4*BATCH];       // xg bwd        [t][3200][32]
__device__ float g_h0T [(size_t)T_SEQ*L1K*BATCH];      // layer0 out    [t][1600][32]
__device__ float g_h1T [(size_t)T_SEQ*L1K*BATCH];      // layer1 out    [t][1600][32]
__device__ float g_hstate[2*2*HID*BATCH];              // [dir][parity][b][800]
__device__ float g_dih [T_SEQ*BATCH*3];
__device__ unsigned g_bar_cnt;
__device__ volatile unsigned g_bar_gen;

// ---------------- f32x2 packed helpers --------------------------------------
__device__ __forceinline__ void ffma2(unsigned long long& d,
                                      unsigned long long a, unsigned long long b) {
    asm("fma.rn.f32x2 %0, %1, %2, %0;" : "+l"(d) : "l"(a), "l"(b));
}
__device__ __forceinline__ unsigned long long pack2(float lo, float hi) {
    unsigned long long r;
    asm("mov.b64 %0, {%1,%2};" : "=l"(r) : "f"(lo), "f"(hi));
    return r;
}
__device__ __forceinline__ unsigned long long dup2(float v) {
    unsigned long long r;
    asm("mov.b64 %0, {%1,%1};" : "=l"(r) : "f"(v));
    return r;
}
__device__ __forceinline__ float2 unpack2(unsigned long long v) {
    float2 r;
    asm("mov.b64 {%0,%1}, %2;" : "=f"(r.x), "=f"(r.y) : "l"(v));
    return r;
}

// ---------------- cp.async helpers ------------------------------------------
__device__ __forceinline__ void cp_async16(void* smem_dst, const void* gsrc,
                                           unsigned src_bytes) {
    unsigned s = (unsigned)__cvta_generic_to_shared(smem_dst);
    asm volatile("cp.async.cg.shared.global [%0], [%1], 16, %2;"
                 :: "r"(s), "l"(gsrc), "r"(src_bytes));
}
__device__ __forceinline__ void cp_commit() {
    asm volatile("cp.async.commit_group;");
}
template<int N> __device__ __forceinline__ void cp_wait() {
    asm volatile("cp.async.wait_group %0;" :: "n"(N));
}

// ---------------- build x (embedding + evolutionary concat), TKB layout ----
__global__ __launch_bounds__(256) void build_x_kernel(
        const int* __restrict__ primary,
        const float* __restrict__ evo,
        const float* __restrict__ emb) {
    int t = blockIdx.x;
    for (int idx = threadIdx.x; idx < DIN*BATCH; idx += 256) {
        int d = idx >> 5;
        int b = idx & 31;
        float v;
        if (d < 32) {
            int p = primary[t*BATCH + b];
            v = emb[p*32 + d];
        } else {
            v = evo[((size_t)t*BATCH + b)*21 + (d - 32)];
        }
        g_xT[((size_t)t*DIN + d)*BATCH + b] = v;
    }
}

// ---------------- f32x2 SGEMM v3: cbuf[M][3200] = A_tkb @ B^T + bias --------
// A in TKB layout [T][K][32] (logical row m = t*32+b), B row-major [3200][K].
// A tile: one cp.async.cg 16B per thread into As[k][m] (contiguous along m).
// B tile: one LDG.128 per thread (contiguous along k) when K%4==0, else 4
// scalar LDGs (K=53 rows are NOT 16B aligned) -> 4x STS.32 into Bs[k][n].
// Accumulators pack two consecutive m per f32x2 lane. One sync per K-tile.
__global__ __launch_bounds__(256, 2) void gemm_tkb_kernel(
        const float* __restrict__ Bm, const float* __restrict__ bias,
        int K, int a_sel) {
    const float* __restrict__ A = a_sel ? g_h0T : g_xT;
    __shared__ float As[2][8*GP];
    __shared__ float Bs[2][8*GP];
    int m0 = blockIdx.x * 128;
    int n0 = blockIdx.y * 128;
    int tid = threadIdx.x;
    int tx = tid & 15, ty = tid >> 4;

    // A async-load mapping: thread -> (k row, 4 consecutive m)
    int ka  = tid >> 5;          // 0..7
    int ja  = tid & 31;          // m = 4*ja
    int tta = (m0 >> 5) + (ja >> 3);
    int bba = 4*(ja & 7);
    // B load mapping: thread -> (n row, 4 consecutive k)
    int nb = tid >> 1;           // 0..127
    int kq = (tid & 1) * 4;

    int nt = (K + 7) / 8;
    bool k_vec = ((K & 3) == 0);  // 16B-aligned B rows (uniform branch)

    auto issueA = [&](int kt, int buf) {
        int k = kt*8 + ka;
        int kc = (k < K) ? k : (K - 1);
        unsigned bytes = (k < K) ? 16u : 0u;
        cp_async16(&As[buf][ka*GP + 4*ja],
                   &A[((size_t)tta*K + kc)*BATCH + bba], bytes);
        cp_commit();
    };
    auto loadB = [&](int kt, float4& r) {
        int k = kt*8 + kq;
        const float* src = &Bm[(size_t)(n0 + nb)*K + k];
        if (k_vec && k + 3 < K) {
            r = *(const float4*)src;          // 16B aligned: K%4==0
        } else {
            r.x = (k+0 < K) ? src[0] : 0.f;
            r.y = (k+1 < K) ? src[1] : 0.f;
            r.z = (k+2 < K) ? src[2] : 0.f;
            r.w = (k+3 < K) ? src[3] : 0.f;
        }
    };

    unsigned long long acc2[4][8];
    #pragma unroll
    for (int i = 0; i < 4; i++)
        #pragma unroll
        for (int j = 0; j < 8; j++) acc2[i][j] = 0ULL;

    float4 breg;
    issueA(0, 0);
    loadB(0, breg);

    for (int kt = 0; kt < nt; kt++) {
        int cb = kt & 1;
        {   // stage current B tile into smem (conflict-free via GP pad)
            float* d = &Bs[cb][kq*GP + nb];
            d[0*GP] = breg.x; d[1*GP] = breg.y;
            d[2*GP] = breg.z; d[3*GP] = breg.w;
        }
        cp_wait<0>();            // current As tile arrived
        __syncthreads();
        if (kt + 1 < nt) {
            issueA(kt + 1, cb ^ 1);
            loadB(kt + 1, breg);
        }
        #pragma unroll
        for (int kk = 0; kk < 8; kk++) {
            float4 a0 = *(const float4*)&As[cb][kk*GP + ty*8];
            float4 a1 = *(const float4*)&As[cb][kk*GP + ty*8 + 4];
            float4 b0 = *(const float4*)&Bs[cb][kk*GP + tx*8];
            float4 b1 = *(const float4*)&Bs[cb][kk*GP + tx*8 + 4];
            unsigned long long ap[4];
            ap[0] = pack2(a0.x, a0.y); ap[1] = pack2(a0.z, a0.w);
            ap[2] = pack2(a1.x, a1.y); ap[3] = pack2(a1.z, a1.w);
            unsigned long long bd[8];
            bd[0] = dup2(b0.x); bd[1] = dup2(b0.y);
            bd[2] = dup2(b0.z); bd[3] = dup2(b0.w);
            bd[4] = dup2(b1.x); bd[5] = dup2(b1.y);
            bd[6] = dup2(b1.z); bd[7] = dup2(b1.w);
            #pragma unroll
            for (int i = 0; i < 4; i++)
                #pragma unroll
                for (int j = 0; j < 8; j++)
                    ffma2(acc2[i][j], ap[i], bd[j]);
        }
        __syncthreads();
    }

    #pragma unroll
    for (int j = 0; j < 8; j++) {
        int col = n0 + tx*8 + j;
        float bv = __ldg(&bias[col]);
        #pragma unroll
        for (int i = 0; i < 4; i++) {
            float2 v = unpack2(acc2[i][j]);
            int row = m0 + ty*8 + 2*i;
            g_cbuf[(size_t)row*G4 + col]       = v.x + bv;
            g_cbuf[(size_t)(row+1)*G4 + col]   = v.y + bv;
        }
    }
}

// ---------------- transpose g_cbuf [t*32+b][3200] -> xgT [t][3200][32] ------
__global__ void transpose_kernel(int dst_sel) {
    float* __restrict__ dst = dst_sel ? g_xgTb : g_xgTf;
    __shared__ float sm[32][33];
    int t  = blockIdx.x;
    int n0 = blockIdx.y * 32;
    int x = threadIdx.x, y = threadIdx.y;   // 32 x 8
    #pragma unroll
    for (int i = 0; i < 4; i++) {
        int b = y + i*8;
        sm[b][x] = g_cbuf[((size_t)t*BATCH + b)*G4 + n0 + x];
    }
    __syncthreads();
    #pragma unroll
    for (int i = 0; i < 4; i++) {
        int n = y + i*8;
        dst[((size_t)t*G4 + n0 + n)*BATCH + x] = sm[x][n];
    }
}

// ---------------- device-wide barrier (generation based) --------------------
__device__ __forceinline__ void grid_barrier() {
    __syncthreads();
    if (threadIdx.x == 0) {
        unsigned my = g_bar_gen;
        __threadfence();
        if (atomicAdd(&g_bar_cnt, 1) == NB_LSTM - 1) {
            g_bar_cnt = 0;
            __threadfence();
            g_bar_gen = my + 1;
        } else {
            while (g_bar_gen == my) { }
            __threadfence();
        }
    }
    __syncthreads();
}

// ---------------- persistent bidirectional LSTM layer -----------------------
// 148 blocks: 74 per direction. Block owns nh (10-11) hidden units = 4*nh gate
// rows. Each warp sweeps up to 6 rows per k-pass; rows 0..31 cached in smem
// (warp-uniform broadcast), rows 32..47 streamed from L2. Packed fma.rn.f32x2
// with the k-pair packed: h stored [b][k] so LDS.128 gives natural f32x2 pairs,
// and row-major Whh float4s are natural f32x2 pairs.
__global__ __launch_bounds__(256, 1) void lstm_kernel(
        const float* __restrict__ Whhf, const float* __restrict__ Whhb,
        int layer) {
    extern __shared__ float smem[];
    float* hs  = smem;                        // [32][HSTR] prev h, [b][k]
    float* wsm = hs + 32*HSTR;                // [32][800] cached Whh rows
    float* pre = wsm + 32*HID;                // [44*32] gate pre-activations
    float* csm = pre + 44*BATCH;              // [11*32] cell state
    float* hout = layer ? g_h1T : g_h0T;

    int bid = blockIdx.x;
    int dir = (bid >= 74) ? 1 : 0;
    int lb  = dir ? bid - 74 : bid;           // 0..73
    int nh, h0;
    if (lb < 60) { nh = 11; h0 = lb*11; }
    else         { nh = 10; h0 = 660 + (lb-60)*10; }
    const float* __restrict__ xgT = dir ? g_xgTb : g_xgTf;
    const float* __restrict__ Whh = dir ? Whhb : Whhf;

    int tid = threadIdx.x;
    int lane = tid & 31, w = tid >> 5;
    int nrows = nh * 4;                       // 40 or 44

    int grows[6];
    bool valid[6];
    #pragma unroll
    for (int s = 0; s < 6; s++) {
        int lr = w + 8*s;
        bool v = lr < nrows;
        int lru = v ? lr : 0;
        grows[s] = (lru & 3)*HID + h0 + (lru >> 2);
        valid[s] = v;
    }
    const float* wq0 = Whh + (size_t)grows[4]*HID;   // streamed rows (s=4,5)
    const float* wq1 = Whh + (size_t)grows[5]*HID;

    // preload cached weight rows lr = 0..31 (always valid: nrows >= 40)
    for (int lr = 0; lr < 32; lr++) {
        int g = (lr & 3)*HID + h0 + (lr >> 2);
        const float* src = Whh + (size_t)g*HID;
        for (int k = tid; k < HID; k += 256) wsm[lr*HID + k] = src[k];
    }

    // zero-init c (smem) and own slots of h parity-0 buffer [b][k]
    for (int i = tid; i < nh*BATCH; i += 256) {
        csm[i] = 0.f;
        int hl = i >> 5, b = i & 31;
        g_hstate[(size_t)(dir*2 + 0)*HID*BATCH + b*HID + (h0 + hl)] = 0.f;
    }
    grid_barrier();

    for (int t = 0; t < T_SEQ; t++) {
        int te = dir ? (T_SEQ - 1 - t) : t;
        int p = t & 1;
        // stage previous h [b][k] into smem (coalesced LDG, conflict-free STS)
        const float* hsg = &g_hstate[(size_t)(dir*2 + p)*HID*BATCH];
        for (int i = tid; i < HID*BATCH; i += 256) {
            int b = i / HID, k = i - b*HID;
            hs[b*HSTR + k] = __ldcg(&hsg[i]);
        }
        __syncthreads();

        // phase A: gate pre-activations, 6 rows per warp, packed f32x2
        unsigned long long a0[6], a1[6];
        #pragma unroll
        for (int s = 0; s < 6; s++) {
            float xg = xgT[((size_t)te*G4 + grows[s])*BATCH + lane];
            a0[s] = pack2(xg, 0.f);
            a1[s] = 0ULL;
        }
        const float* hrow = &hs[lane*HSTR];
        #pragma unroll 4
        for (int k = 0; k < HID; k += 4) {
            ulonglong2 hv = *(const ulonglong2*)(hrow + k);
            #pragma unroll
            for (int s = 0; s < 4; s++) {
                ulonglong2 wv = *(const ulonglong2*)&wsm[(w + 8*s)*HID + k];
                ffma2(a0[s], hv.x, wv.x);
                ffma2(a1[s], hv.y, wv.y);
            }
            {
                ulonglong2 wv = *(const ulonglong2*)(wq0 + k);
                ffma2(a0[4], hv.x, wv.x);
                ffma2(a1[4], hv.y, wv.y);
            }
            {
                ulonglong2 wv = *(const ulonglong2*)(wq1 + k);
                ffma2(a0[5], hv.x, wv.x);
                ffma2(a1[5], hv.y, wv.y);
            }
        }
        #pragma unroll
        for (int s = 0; s < 6; s++) {
            if (valid[s]) {
                float2 x = unpack2(a0[s]);
                float2 y = unpack2(a1[s]);
                pre[(w + 8*s)*BATCH + lane] = (x.x + x.y) + (y.x + y.y);
            }
        }
        __syncthreads();

        // phase B: gate nonlinearity + state update
        for (int i = tid; i < nh*BATCH; i += 256) {
            int hl = i >> 5, b = i & 31;
            float iv = pre[(hl*4+0)*BATCH + b];
            float fv = pre[(hl*4+1)*BATCH + b];
            float gv = pre[(hl*4+2)*BATCH + b];
            float ov = pre[(hl*4+3)*BATCH + b];
            float si = 1.f/(1.f + expf(-iv));
            float sf = 1.f/(1.f + expf(-fv));
            float so = 1.f/(1.f + expf(-ov));
            float c  = sf*csm[i] + si*tanhf(gv);
            float hv = so*tanhf(c);
            csm[i] = c;
            int hi = h0 + hl;
            g_hstate[(size_t)(dir*2 + (1-p))*HID*BATCH + b*HID + hi] = hv;
            hout[((size_t)te*L1K + dir*HID + hi)*BATCH + b] = hv;
        }
        grid_barrier();
    }
}

// ---------------- FC + softmax-free angularization -> dihedrals -------------
__global__ __launch_bounds__(256) void fc_dih_kernel(
        const float* __restrict__ fcW, const float* __restrict__ fcb,
        const float* __restrict__ alphabet) {
    __shared__ float chunk[256*BATCH];   // 32KB feature chunk [k][b]
    __shared__ float lsm[NA*BATCH];
    __shared__ float sn[NA*3], cs[NA*3];
    int t = blockIdx.x;
    int tid = threadIdx.x;
    int lane = tid & 31, w = tid >> 5;

    float acc[8];
    #pragma unroll
    for (int i = 0; i < 8; i++) acc[i] = 0.f;

    for (int c0 = 0; c0 < RNNOUT; c0 += 256) {
        int clen = RNNOUT - c0; if (clen > 256) clen = 256;
        for (int idx = tid; idx < clen*BATCH; idx += 256) {
            int k = idx >> 5, b = idx & 31;
            int f = c0 + k;
            chunk[idx] = (f < L1K)
                ? g_h1T[((size_t)t*L1K + f)*BATCH + b]
                : g_xT [((size_t)t*DIN + (f - L1K))*BATCH + b];
        }
        __syncthreads();
        #pragma unroll
        for (int i = 0; i < 8; i++) {
            int a = w*8 + i;
            if (a < NA) {
                const float* wr = fcW + (size_t)a*RNNOUT + c0;
                float s = acc[i];
                #pragma unroll 4
                for (int k = 0; k < clen; k++)
                    s = fmaf(__ldg(wr + k), chunk[k*BATCH + lane], s);
                acc[i] = s;
            }
        }
        __syncthreads();
    }
    #pragma unroll
    for (int i = 0; i < 8; i++) {
        int a = w*8 + i;
        if (a < NA) lsm[a*BATCH + lane] = acc[i] + fcb[a];
    }
    for (int i = tid; i < NA*3; i += 256) {
        float v = alphabet[i];
        sn[i] = sinf(v); cs[i] = cosf(v);
    }
    __syncthreads();
    if (tid < 96) {
        int b = tid & 31, j = tid >> 5;
        float ss = 0.f, cc = 0.f;
        for (int a = 0; a < NA; a++) {
            float e = expf(lsm[a*BATCH + b]);   // softmax Z cancels in atan2
            ss = fmaf(e, sn[a*3 + j], ss);
            cc = fmaf(e, cs[a*3 + j], cc);
        }
        g_dih[((size_t)t*BATCH + b)*3 + j] = atan2f(ss, cc);
    }
}

// ---------------- dihedral -> points -> NeRF coordinate extension -----------
__global__ void geometry_kernel(float* __restrict__ out) {
    int b = threadIdx.x;   // 0..31, one lane per batch element
    const float PI = 3.14159265358979323846f;
    float BL[3] = {145.801f, 152.326f, 132.868f};
    float BA[3] = {2.124f, 1.941f, 2.028f};
    float rct[3], rst[3];
    #pragma unroll
    for (int j = 0; j < 3; j++) {
        rct[j] = BL[j]*cosf(PI - BA[j]);
        rst[j] = BL[j]*sinf(PI - BA[j]);
    }
    float ax = -sqrtf(0.5f), ay = sqrtf(1.5f), az = 0.f;
    float bx = -sqrtf(2.0f), by = 0.f,        bz = 0.f;
    float cx = 0.f, cy = 0.f, cz = 0.f;

    for (int i = 0; i < 3*T_SEQ; i++) {
        int t = i / 3, j = i - 3*t;
        float d  = g_dih[((size_t)t*BATCH + b)*3 + j];
        float p0 = rct[j];
        float p1 = cosf(d)*rst[j];
        float p2 = sinf(d)*rst[j];

        float ux = cx-bx, uy = cy-by, uz = cz-bz;
        float inv = 1.f/sqrtf(ux*ux + uy*uy + uz*uz + 1e-12f);
        float bcx = ux*inv, bcy = uy*inv, bcz = uz*inv;

        float vx = bx-ax, vy = by-ay, vz = bz-az;
        float nx0 = vy*bcz - vz*bcy;
        float ny0 = vz*bcx - vx*bcz;
        float nz0 = vx*bcy - vy*bcx;
        float inv2 = 1.f/sqrtf(nx0*nx0 + ny0*ny0 + nz0*nz0 + 1e-12f);
        float nx = nx0*inv2, ny = ny0*inv2, nz = nz0*inv2;

        float mx = ny*bcz - nz*bcy;
        float my = nz*bcx - nx*bcz;
        float mz = nx*bcy - ny*bcx;

        float ox = cx + p0*bcx + p1*mx + p2*nx;
        float oy = cy + p0*bcy + p1*my + p2*ny;
        float oz = cz + p0*bcz + p1*mz + p2*nz;

        size_t o = ((size_t)i*BATCH + b)*3;
        out[o+0] = ox; out[o+1] = oy; out[o+2] = oz;

        ax = bx; ay = by; az = bz;
        bx = cx; by = cy; bz = cz;
        cx = ox; cy = oy; cz = oz;
    }
}

// ---------------- launch ----------------------------------------------------
extern "C" void kernel_launch(void* const* d_in, const int* in_sizes, int n_in,
                              void* d_out, int out_size) {
    const int*   primary = (const int*)  d_in[0];
    const float* evo     = (const float*)d_in[1];
    // d_in[2] = seq_length (fixed 700, ignored)
    const float* emb     = (const float*)d_in[3];
    const float* Wih0f   = (const float*)d_in[4];
    const float* Whh0f   = (const float*)d_in[5];
    const float* b0f     = (const float*)d_in[6];
    const float* Wih0b   = (const float*)d_in[7];
    const float* Whh0b   = (const float*)d_in[8];
    const float* b0b     = (const float*)d_in[9];
    const float* Wih1f   = (const float*)d_in[10];
    const float* Whh1f   = (const float*)d_in[11];
    const float* b1f     = (const float*)d_in[12];
    const float* Wih1b   = (const float*)d_in[13];
    const float* Whh1b   = (const float*)d_in[14];
    const float* b1b     = (const float*)d_in[15];
    const float* fcW     = (const float*)d_in[16];
    const float* fcb     = (const float*)d_in[17];
    const float* alphabet= (const float*)d_in[18];
    float* out = (float*)d_out;

    cudaFuncSetAttribute(lstm_kernel,
                         cudaFuncAttributeMaxDynamicSharedMemorySize, LSTM_SMEM);

    dim3 ggrid(175, 25);           // 22400/128, 3200/128
    dim3 tgrid(T_SEQ, 100);        // 3200/32
    dim3 tblk(32, 8);

    build_x_kernel<<<T_SEQ, 256>>>(primary, evo, emb);

    // layer 0 input projections
    gemm_tkb_kernel<<<ggrid, 256>>>(Wih0f, b0f, DIN, 0);
    transpose_kernel<<<tgrid, tblk>>>(0);
    gemm_tkb_kernel<<<ggrid, 256>>>(Wih0b, b0b, DIN, 0);
    transpose_kernel<<<tgrid, tblk>>>(1);
    lstm_kernel<<<NB_LSTM, 256, LSTM_SMEM>>>(Whh0f, Whh0b, 0);

    // layer 1 input projections
    gemm_tkb_kernel<<<ggrid, 256>>>(Wih1f, b1f, L1K, 1);
    transpose_kernel<<<tgrid, tblk>>>(0);
    gemm_tkb_kernel<<<ggrid, 256>>>(Wih1b, b1b, L1K, 1);
    transpose_kernel<<<tgrid, tblk>>>(1);
    lstm_kernel<<<NB_LSTM, 256, LSTM_SMEM>>>(Whh1f, Whh1b, 1);

    fc_dih_kernel<<<T_SEQ, 256>>>(fcW, fcb, alphabet);
    geometry_kernel<<<1, 32>>>(out);
}

// round 15
// speedup vs baseline: 1.7122x; 1.0157x over previous
#include <cuda_runtime.h>
#include <math.h>

#define T_SEQ 700
#define BATCH 32
#define HID 800
#define DIN 53
#define G4 3200       // 4*HID
#define L1K 1600      // 2*HID
#define NA 60
#define RNNOUT 1653   // 2*HID + DIN
#define NB_LSTM 148
#define NB_DIR 74
#define KCH 160       // LSTM staging chunk (k per chunk), 5 chunks of 160 = 800
#define HSTR 804      // padded h stride (floats): 16B-aligned, conflict-free LDS.128 phases
#define GP 132        // GEMM smem row pad (floats): 16B-aligned, kills STS/LDS conflicts
// smem floats: hs 32*804 + wsm 32*800 + pre 44*32 + csm 11*32
#define LSTM_SMEM ((32*HSTR + 32*HID + 44*BATCH + 11*BATCH) * 4)

// ---------------- scratch (static device allocations) ----------------
__device__ float g_xT  [(size_t)T_SEQ*DIN*BATCH];      // x transposed  [t][53][32]
__device__ float g_cbuf[(size_t)T_SEQ*BATCH*G4];       // GEMM output   [t*32+b][3200]
__device__ float g_xgTf[(size_t)T_SEQ*G4*BATCH];       // xg fwd        [t][3200][32]
__device__ float g_xgTb[(size_t)T_SEQ*G4*BATCH];       // xg bwd        [t][3200][32]
__device__ float g_h0T [(size_t)T_SEQ*L1K*BATCH];      // layer0 out    [t][1600][32]
__device__ float g_h1T [(size_t)T_SEQ*L1K*BATCH];      // layer1 out    [t][1600][32]
__device__ float g_hstate[2*2*HID*BATCH];              // [dir][parity][b][800]
__device__ float g_dih [T_SEQ*BATCH*3];
__device__ unsigned g_bar_cnt2[2];
__device__ volatile unsigned g_bar_gen2[2];

// ---------------- f32x2 packed helpers --------------------------------------
__device__ __forceinline__ void ffma2(unsigned long long& d,
                                      unsigned long long a, unsigned long long b) {
    asm("fma.rn.f32x2 %0, %1, %2, %0;" : "+l"(d) : "l"(a), "l"(b));
}
__device__ __forceinline__ unsigned long long pack2(float lo, float hi) {
    unsigned long long r;
    asm("mov.b64 %0, {%1,%2};" : "=l"(r) : "f"(lo), "f"(hi));
    return r;
}
__device__ __forceinline__ unsigned long long dup2(float v) {
    unsigned long long r;
    asm("mov.b64 %0, {%1,%1};" : "=l"(r) : "f"(v));
    return r;
}
__device__ __forceinline__ float2 unpack2(unsigned long long v) {
    float2 r;
    asm("mov.b64 {%0,%1}, %2;" : "=f"(r.x), "=f"(r.y) : "l"(v));
    return r;
}

// ---------------- cp.async helpers ------------------------------------------
__device__ __forceinline__ void cp_async16(void* smem_dst, const void* gsrc,
                                           unsigned src_bytes) {
    unsigned s = (unsigned)__cvta_generic_to_shared(smem_dst);
    asm volatile("cp.async.cg.shared.global [%0], [%1], 16, %2;"
                 :: "r"(s), "l"(gsrc), "r"(src_bytes));
}
__device__ __forceinline__ void cp_commit() {
    asm volatile("cp.async.commit_group;");
}
template<int N> __device__ __forceinline__ void cp_wait() {
    asm volatile("cp.async.wait_group %0;" :: "n"(N));
}

// ---------------- build x (embedding + evolutionary concat), TKB layout ----
__global__ __launch_bounds__(256) void build_x_kernel(
        const int* __restrict__ primary,
        const float* __restrict__ evo,
        const float* __restrict__ emb) {
    int t = blockIdx.x;
    for (int idx = threadIdx.x; idx < DIN*BATCH; idx += 256) {
        int d = idx >> 5;
        int b = idx & 31;
        float v;
        if (d < 32) {
            int p = primary[t*BATCH + b];
            v = emb[p*32 + d];
        } else {
            v = evo[((size_t)t*BATCH + b)*21 + (d - 32)];
        }
        g_xT[((size_t)t*DIN + d)*BATCH + b] = v;
    }
}

// ---------------- f32x2 SGEMM v4: cbuf[M][3200] = A_tkb @ B^T + bias --------
// A in TKB layout [T][K][32] (row m = t*32+b), B row-major [3200][K].
// A: 3-stage cp.async (one 16B op/thread/tile). B: register relay prefetched
// 2 tiles ahead (LDG.128 when K%4==0, scalar otherwise — K=53 rows are NOT
// 16B aligned), staged to smem via 4x STS.32. One __syncthreads per K-tile.
__global__ __launch_bounds__(256, 2) void gemm_tkb_kernel(
        const float* __restrict__ Bm, const float* __restrict__ bias,
        int K, int a_sel) {
    const float* __restrict__ A = a_sel ? g_h0T : g_xT;
    __shared__ float As[3][8*GP];
    __shared__ float Bs[2][8*GP];
    int m0 = blockIdx.x * 128;
    int n0 = blockIdx.y * 128;
    int tid = threadIdx.x;
    int tx = tid & 15, ty = tid >> 4;

    // A async-load mapping: thread -> (k row, 4 consecutive m)
    int ka  = tid >> 5;          // 0..7
    int ja  = tid & 31;          // m = 4*ja
    int tta = (m0 >> 5) + (ja >> 3);
    int bba = 4*(ja & 7);
    // B load mapping: thread -> (n row, 4 consecutive k)
    int nb = tid >> 1;           // 0..127
    int kq = (tid & 1) * 4;

    int nt = (K + 7) / 8;
    bool k_vec = ((K & 3) == 0);  // 16B-aligned B rows (uniform branch)

    auto issueA = [&](int kt, int buf) {
        int k = kt*8 + ka;
        int kc = (k < K) ? k : (K - 1);
        unsigned bytes = (k < K) ? 16u : 0u;
        cp_async16(&As[buf][ka*GP + 4*ja],
                   &A[((size_t)tta*K + kc)*BATCH + bba], bytes);
        cp_commit();
    };
    auto loadB = [&](int kt, float4& r) {
        int k = kt*8 + kq;
        const float* src = &Bm[(size_t)(n0 + nb)*K + k];
        if (k_vec && k + 3 < K) {
            r = *(const float4*)src;          // 16B aligned: K%4==0
        } else {
            r.x = (k+0 < K) ? src[0] : 0.f;
            r.y = (k+1 < K) ? src[1] : 0.f;
            r.z = (k+2 < K) ? src[2] : 0.f;
            r.w = (k+3 < K) ? src[3] : 0.f;
        }
    };

    unsigned long long acc2[4][8];
    #pragma unroll
    for (int i = 0; i < 4; i++)
        #pragma unroll
        for (int j = 0; j < 8; j++) acc2[i][j] = 0ULL;

    float4 breg[2];
    issueA(0, 0);
    if (nt > 1) issueA(1, 1);
    loadB(0, breg[0]);
    if (nt > 1) loadB(1, breg[1]);

    for (int kt = 0; kt < nt; kt++) {
        int cb = kt % 3;
        int bb = kt & 1;
        {   // stage current B tile into smem (conflict-free via GP pad)
            float4 bv = breg[bb];
            float* d = &Bs[bb][kq*GP + nb];
            d[0*GP] = bv.x; d[1*GP] = bv.y;
            d[2*GP] = bv.z; d[3*GP] = bv.w;
        }
        if (kt < nt - 1) cp_wait<1>(); else cp_wait<0>();  // A(kt) arrived
        __syncthreads();
        if (kt + 2 < nt) {
            issueA(kt + 2, (kt + 2) % 3);
            loadB(kt + 2, breg[bb]);       // slot just consumed by stageB
        }
        #pragma unroll
        for (int kk = 0; kk < 8; kk++) {
            float4 a0 = *(const float4*)&As[cb][kk*GP + ty*8];
            float4 a1 = *(const float4*)&As[cb][kk*GP + ty*8 + 4];
            float4 b0 = *(const float4*)&Bs[bb][kk*GP + tx*8];
            float4 b1 = *(const float4*)&Bs[bb][kk*GP + tx*8 + 4];
            unsigned long long ap[4];
            ap[0] = pack2(a0.x, a0.y); ap[1] = pack2(a0.z, a0.w);
            ap[2] = pack2(a1.x, a1.y); ap[3] = pack2(a1.z, a1.w);
            unsigned long long bd[8];
            bd[0] = dup2(b0.x); bd[1] = dup2(b0.y);
            bd[2] = dup2(b0.z); bd[3] = dup2(b0.w);
            bd[4] = dup2(b1.x); bd[5] = dup2(b1.y);
            bd[6] = dup2(b1.z); bd[7] = dup2(b1.w);
            #pragma unroll
            for (int i = 0; i < 4; i++)
                #pragma unroll
                for (int j = 0; j < 8; j++)
                    ffma2(acc2[i][j], ap[i], bd[j]);
        }
        __syncthreads();
    }

    #pragma unroll
    for (int j = 0; j < 8; j++) {
        int col = n0 + tx*8 + j;
        float bv = __ldg(&bias[col]);
        #pragma unroll
        for (int i = 0; i < 4; i++) {
            float2 v = unpack2(acc2[i][j]);
            int row = m0 + ty*8 + 2*i;
            g_cbuf[(size_t)row*G4 + col]       = v.x + bv;
            g_cbuf[(size_t)(row+1)*G4 + col]   = v.y + bv;
        }
    }
}

// ---------------- transpose g_cbuf [t*32+b][3200] -> xgT [t][3200][32] ------
__global__ void transpose_kernel(int dst_sel) {
    float* __restrict__ dst = dst_sel ? g_xgTb : g_xgTf;
    __shared__ float sm[32][33];
    int t  = blockIdx.x;
    int n0 = blockIdx.y * 32;
    int x = threadIdx.x, y = threadIdx.y;   // 32 x 8
    #pragma unroll
    for (int i = 0; i < 4; i++) {
        int b = y + i*8;
        sm[b][x] = g_cbuf[((size_t)t*BATCH + b)*G4 + n0 + x];
    }
    __syncthreads();
    #pragma unroll
    for (int i = 0; i < 4; i++) {
        int n = y + i*8;
        dst[((size_t)t*G4 + n0 + n)*BATCH + x] = sm[x][n];
    }
}

// ---------------- per-direction device-wide barrier (generation based) ------
__device__ __forceinline__ void grid_barrier_dir(int dir) {
    __syncthreads();
    if (threadIdx.x == 0) {
        unsigned my = g_bar_gen2[dir];
        __threadfence();
        if (atomicAdd(&g_bar_cnt2[dir], 1) == NB_DIR - 1) {
            g_bar_cnt2[dir] = 0;
            __threadfence();
            g_bar_gen2[dir] = my + 1;
        } else {
            while (g_bar_gen2[dir] == my) { }
            __threadfence();
        }
    }
    __syncthreads();
}

// ---------------- persistent bidirectional LSTM layer -----------------------
// 148 blocks: 74 per direction (independent barriers). Block owns nh (10-11)
// hidden units = 4*nh gate rows; each warp sweeps up to 6 rows. Rows 0..31
// have Whh cached in smem; rows 32..47 stream from L2. Previous h is staged
// [b][k] into smem via cp.async.cg in 5 chunks of k=160, overlapped with the
// packed fma.rn.f32x2 accumulation of earlier chunks.
__global__ __launch_bounds__(256, 1) void lstm_kernel(
        const float* __restrict__ Whhf, const float* __restrict__ Whhb,
        int layer) {
    extern __shared__ float smem[];
    float* hs  = smem;                        // [32][HSTR] prev h, [b][k]
    float* wsm = hs + 32*HSTR;                // [32][800] cached Whh rows
    float* pre = wsm + 32*HID;                // [44*32] gate pre-activations
    float* csm = pre + 44*BATCH;              // [11*32] cell state
    float* hout = layer ? g_h1T : g_h0T;

    int bid = blockIdx.x;
    int dir = (bid >= NB_DIR) ? 1 : 0;
    int lb  = dir ? bid - NB_DIR : bid;       // 0..73
    int nh, h0;
    if (lb < 60) { nh = 11; h0 = lb*11; }
    else         { nh = 10; h0 = 660 + (lb-60)*10; }
    const float* __restrict__ xgT = dir ? g_xgTb : g_xgTf;
    const float* __restrict__ Whh = dir ? Whhb : Whhf;

    int tid = threadIdx.x;
    int lane = tid & 31, w = tid >> 5;
    int nrows = nh * 4;                       // 40 or 44

    int grows[6];
    bool valid[6];
    #pragma unroll
    for (int s = 0; s < 6; s++) {
        int lr = w + 8*s;
        bool v = lr < nrows;
        int lru = v ? lr : 0;
        grows[s] = (lru & 3)*HID + h0 + (lru >> 2);
        valid[s] = v;
    }
    const float* wq0 = Whh + (size_t)grows[4]*HID;   // streamed rows (s=4,5)
    const float* wq1 = Whh + (size_t)grows[5]*HID;

    // preload cached weight rows lr = 0..31 (always valid: nrows >= 40)
    for (int lr = 0; lr < 32; lr++) {
        int g = (lr & 3)*HID + h0 + (lr >> 2);
        const float* src = Whh + (size_t)g*HID;
        for (int k = tid; k < HID; k += 256) wsm[lr*HID + k] = src[k];
    }

    // zero-init c (smem) and own slots of h parity-0 buffer [b][k]
    for (int i = tid; i < nh*BATCH; i += 256) {
        csm[i] = 0.f;
        int hl = i >> 5, b = i & 31;
        g_hstate[(size_t)(dir*2 + 0)*HID*BATCH + b*HID + (h0 + hl)] = 0.f;
    }
    grid_barrier_dir(dir);

    for (int t = 0; t < T_SEQ; t++) {
        int te = dir ? (T_SEQ - 1 - t) : t;
        int p = t & 1;
        const float* hsg = &g_hstate[(size_t)(dir*2 + p)*HID*BATCH];

        // issue staging of prev h in 5 k-chunks (cp.async.cg: L2, coherent)
        #pragma unroll
        for (int c = 0; c < 5; c++) {
            int k0 = c*KCH;
            #pragma unroll
            for (int j = 0; j < 5; j++) {
                int q  = tid + j*256;         // 0..1279
                int b  = q / 40;
                int kk = (q - b*40)*4;
                cp_async16(&hs[b*HSTR + k0 + kk], &hsg[b*HID + k0 + kk], 16u);
            }
            cp_commit();
        }

        // init accumulators with xg
        unsigned long long a0[6], a1[6];
        #pragma unroll
        for (int s = 0; s < 6; s++) {
            float xg = xgT[((size_t)te*G4 + grows[s])*BATCH + lane];
            a0[s] = pack2(xg, 0.f);
            a1[s] = 0ULL;
        }
        const float* hrow = &hs[lane*HSTR];

        // phase A: consume chunks as they land, packed f32x2, 6 rows per warp
        #pragma unroll
        for (int c = 0; c < 5; c++) {
            if      (c == 0) cp_wait<4>();
            else if (c == 1) cp_wait<3>();
            else if (c == 2) cp_wait<2>();
            else if (c == 3) cp_wait<1>();
            else             cp_wait<0>();
            __syncthreads();
            int kend = (c+1)*KCH;
            #pragma unroll 4
            for (int k = c*KCH; k < kend; k += 4) {
                ulonglong2 hv = *(const ulonglong2*)(hrow + k);
                #pragma unroll
                for (int s = 0; s < 4; s++) {
                    ulonglong2 wv = *(const ulonglong2*)&wsm[(w + 8*s)*HID + k];
                    ffma2(a0[s], hv.x, wv.x);
                    ffma2(a1[s], hv.y, wv.y);
                }
                {
                    ulonglong2 wv = *(const ulonglong2*)(wq0 + k);
                    ffma2(a0[4], hv.x, wv.x);
                    ffma2(a1[4], hv.y, wv.y);
                }
                {
                    ulonglong2 wv = *(const ulonglong2*)(wq1 + k);
                    ffma2(a0[5], hv.x, wv.x);
                    ffma2(a1[5], hv.y, wv.y);
                }
            }
        }
        #pragma unroll
        for (int s = 0; s < 6; s++) {
            if (valid[s]) {
                float2 x = unpack2(a0[s]);
                float2 y = unpack2(a1[s]);
                pre[(w + 8*s)*BATCH + lane] = (x.x + x.y) + (y.x + y.y);
            }
        }
        __syncthreads();

        // phase B: gate nonlinearity + state update
        for (int i = tid; i < nh*BATCH; i += 256) {
            int hl = i >> 5, b = i & 31;
            float iv = pre[(hl*4+0)*BATCH + b];
            float fv = pre[(hl*4+1)*BATCH + b];
            float gv = pre[(hl*4+2)*BATCH + b];
            float ov = pre[(hl*4+3)*BATCH + b];
            float si = 1.f/(1.f + expf(-iv));
            float sf = 1.f/(1.f + expf(-fv));
            float so = 1.f/(1.f + expf(-ov));
            float c  = sf*csm[i] + si*tanhf(gv);
            float hv = so*tanhf(c);
            csm[i] = c;
            int hi = h0 + hl;
            g_hstate[(size_t)(dir*2 + (1-p))*HID*BATCH + b*HID + hi] = hv;
            hout[((size_t)te*L1K + dir*HID + hi)*BATCH + b] = hv;
        }
        grid_barrier_dir(dir);
    }
}

// ---------------- FC + softmax-free angularization -> dihedrals -------------
__global__ __launch_bounds__(256) void fc_dih_kernel(
        const float* __restrict__ fcW, const float* __restrict__ fcb,
        const float* __restrict__ alphabet) {
    __shared__ float chunk[256*BATCH];   // 32KB feature chunk [k][b]
    __shared__ float lsm[NA*BATCH];
    __shared__ float sn[NA*3], cs[NA*3];
    int t = blockIdx.x;
    int tid = threadIdx.x;
    int lane = tid & 31, w = tid >> 5;

    float acc[8];
    #pragma unroll
    for (int i = 0; i < 8; i++) acc[i] = 0.f;

    for (int c0 = 0; c0 < RNNOUT; c0 += 256) {
        int clen = RNNOUT - c0; if (clen > 256) clen = 256;
        for (int idx = tid; idx < clen*BATCH; idx += 256) {
            int k = idx >> 5, b = idx & 31;
            int f = c0 + k;
            chunk[idx] = (f < L1K)
                ? g_h1T[((size_t)t*L1K + f)*BATCH + b]
                : g_xT [((size_t)t*DIN + (f - L1K))*BATCH + b];
        }
        __syncthreads();
        #pragma unroll
        for (int i = 0; i < 8; i++) {
            int a = w*8 + i;
            if (a < NA) {
                const float* wr = fcW + (size_t)a*RNNOUT + c0;
                float s = acc[i];
                #pragma unroll 4
                for (int k = 0; k < clen; k++)
                    s = fmaf(__ldg(wr + k), chunk[k*BATCH + lane], s);
                acc[i] = s;
            }
        }
        __syncthreads();
    }
    #pragma unroll
    for (int i = 0; i < 8; i++) {
        int a = w*8 + i;
        if (a < NA) lsm[a*BATCH + lane] = acc[i] + fcb[a];
    }
    for (int i = tid; i < NA*3; i += 256) {
        float v = alphabet[i];
        sn[i] = sinf(v); cs[i] = cosf(v);
    }
    __syncthreads();
    if (tid < 96) {
        int b = tid & 31, j = tid >> 5;
        float ss = 0.f, cc = 0.f;
        for (int a = 0; a < NA; a++) {
            float e = expf(lsm[a*BATCH + b]);   // softmax Z cancels in atan2
            ss = fmaf(e, sn[a*3 + j], ss);
            cc = fmaf(e, cs[a*3 + j], cc);
        }
        g_dih[((size_t)t*BATCH + b)*3 + j] = atan2f(ss, cc);
    }
}

// ---------------- dihedral -> points -> NeRF coordinate extension -----------
__global__ void geometry_kernel(float* __restrict__ out) {
    int b = threadIdx.x;   // 0..31, one lane per batch element
    const float PI = 3.14159265358979323846f;
    float BL[3] = {145.801f, 152.326f, 132.868f};
    float BA[3] = {2.124f, 1.941f, 2.028f};
    float rct[3], rst[3];
    #pragma unroll
    for (int j = 0; j < 3; j++) {
        rct[j] = BL[j]*cosf(PI - BA[j]);
        rst[j] = BL[j]*sinf(PI - BA[j]);
    }
    float ax = -sqrtf(0.5f), ay = sqrtf(1.5f), az = 0.f;
    float bx = -sqrtf(2.0f), by = 0.f,        bz = 0.f;
    float cx = 0.f, cy = 0.f, cz = 0.f;

    for (int i = 0; i < 3*T_SEQ; i++) {
        int t = i / 3, j = i - 3*t;
        float d  = g_dih[((size_t)t*BATCH + b)*3 + j];
        float p0 = rct[j];
        float p1 = cosf(d)*rst[j];
        float p2 = sinf(d)*rst[j];

        float ux = cx-bx, uy = cy-by, uz = cz-bz;
        float inv = 1.f/sqrtf(ux*ux + uy*uy + uz*uz + 1e-12f);
        float bcx = ux*inv, bcy = uy*inv, bcz = uz*inv;

        float vx = bx-ax, vy = by-ay, vz = bz-az;
        float nx0 = vy*bcz - vz*bcy;
        float ny0 = vz*bcx - vx*bcz;
        float nz0 = vx*bcy - vy*bcx;
        float inv2 = 1.f/sqrtf(nx0*nx0 + ny0*ny0 + nz0*nz0 + 1e-12f);
        float nx = nx0*inv2, ny = ny0*inv2, nz = nz0*inv2;

        float mx = ny*bcz - nz*bcy;
        float my = nz*bcx - nx*bcz;
        float mz = nx*bcy - ny*bcx;

        float ox = cx + p0*bcx + p1*mx + p2*nx;
        float oy = cy + p0*bcy + p1*my + p2*ny;
        float oz = cz + p0*bcz + p1*mz + p2*nz;

        size_t o = ((size_t)i*BATCH + b)*3;
        out[o+0] = ox; out[o+1] = oy; out[o+2] = oz;

        ax = bx; ay = by; az = bz;
        bx = cx; by = cy; bz = cz;
        cx = ox; cy = oy; cz = oz;
    }
}

// ---------------- launch ----------------------------------------------------
extern "C" void kernel_launch(void* const* d_in, const int* in_sizes, int n_in,
                              void* d_out, int out_size) {
    const int*   primary = (const int*)  d_in[0];
    const float* evo     = (const float*)d_in[1];
    // d_in[2] = seq_length (fixed 700, ignored)
    const float* emb     = (const float*)d_in[3];
    const float* Wih0f   = (const float*)d_in[4];
    const float* Whh0f   = (const float*)d_in[5];
    const float* b0f     = (const float*)d_in[6];
    const float* Wih0b   = (const float*)d_in[7];
    const float* Whh0b   = (const float*)d_in[8];
    const float* b0b     = (const float*)d_in[9];
    const float* Wih1f   = (const float*)d_in[10];
    const float* Whh1f   = (const float*)d_in[11];
    const float* b1f     = (const float*)d_in[12];
    const float* Wih1b   = (const float*)d_in[13];
    const float* Whh1b   = (const float*)d_in[14];
    const float* b1b     = (const float*)d_in[15];
    const float* fcW     = (const float*)d_in[16];
    const float* fcb     = (const float*)d_in[17];
    const float* alphabet= (const float*)d_in[18];
    float* out = (float*)d_out;

    cudaFuncSetAttribute(lstm_kernel,
                         cudaFuncAttributeMaxDynamicSharedMemorySize, LSTM_SMEM);

    dim3 ggrid(175, 25);           // 22400/128, 3200/128
    dim3 tgrid(T_SEQ, 100);        // 3200/32
    dim3 tblk(32, 8);

    build_x_kernel<<<T_SEQ, 256>>>(primary, evo, emb);

    // layer 0 input projections
    gemm_tkb_kernel<<<ggrid, 256>>>(Wih0f, b0f, DIN, 0);
    transpose_kernel<<<tgrid, tblk>>>(0);
    gemm_tkb_kernel<<<ggrid, 256>>>(Wih0b, b0b, DIN, 0);
    transpose_kernel<<<tgrid, tblk>>>(1);
    lstm_kernel<<<NB_LSTM, 256, LSTM_SMEM>>>(Whh0f, Whh0b, 0);

    // layer 1 input projections
    gemm_tkb_kernel<<<ggrid, 256>>>(Wih1f, b1f, L1K, 1);
    transpose_kernel<<<tgrid, tblk>>>(0);
    gemm_tkb_kernel<<<ggrid, 256>>>(Wih1b, b1b, L1K, 1);
    transpose_kernel<<<tgrid, tblk>>>(1);
    lstm_kernel<<<NB_LSTM, 256, LSTM_SMEM>>>(Whh1f, Whh1b, 1);

    fc_dih_kernel<<<T_SEQ, 256>>>(fcW, fcb, alphabet);
    geometry_kernel<<<1, 32>>>(out);
}

// round 17
// speedup vs baseline: 2.0922x; 1.2219x over previous
#include <cuda_runtime.h>
#include <math.h>

#define T_SEQ 700
#define BATCH 32
#define HID 800
#define DIN 53
#define G4 3200       // 4*HID
#define L1K 1600      // 2*HID
#define NA 60
#define RNNOUT 1653   // 2*HID + DIN
#define NB_LSTM 148
#define NB_DIR 74
#define KCH 160       // LSTM staging chunk (k per chunk), 5 chunks of 160 = 800
#define RCH 164       // ring chunk row stride (floats): 656B = 5*128+16 -> conflict-free
#define RSLOT (32*RCH)
#define GP 132        // GEMM smem row pad (floats): 16B-aligned, kills STS/LDS conflicts
// smem floats: ring 3*32*164 + wsm 44*800 + pre 44*32 + csm 11*32
#define LSTM_SMEM ((3*RSLOT + 44*HID + 44*BATCH + 11*BATCH) * 4)

// ---------------- scratch (static device allocations) ----------------
__device__ float g_xT  [(size_t)T_SEQ*DIN*BATCH];      // x transposed  [t][53][32]
__device__ float g_cbuf[(size_t)T_SEQ*BATCH*G4];       // GEMM output   [t*32+b][3200]
__device__ float g_xgTf[(size_t)T_SEQ*G4*BATCH];       // xg fwd        [t][3200][32]
__device__ float g_xgTb[(size_t)T_SEQ*G4*BATCH];       // xg bwd        [t][3200][32]
__device__ float g_h0T [(size_t)T_SEQ*L1K*BATCH];      // layer0 out    [t][1600][32]
__device__ float g_h1T [(size_t)T_SEQ*L1K*BATCH];      // layer1 out    [t][1600][32]
__device__ float g_hstate[2*2*HID*BATCH];              // [dir][parity][b][800]
__device__ float g_dih [T_SEQ*BATCH*3];
__device__ unsigned g_bar_cnt2[2];
__device__ volatile unsigned g_bar_gen2[2];

// ---------------- f32x2 packed helpers --------------------------------------
__device__ __forceinline__ void ffma2(unsigned long long& d,
                                      unsigned long long a, unsigned long long b) {
    asm("fma.rn.f32x2 %0, %1, %2, %0;" : "+l"(d) : "l"(a), "l"(b));
}
__device__ __forceinline__ unsigned long long pack2(float lo, float hi) {
    unsigned long long r;
    asm("mov.b64 %0, {%1,%2};" : "=l"(r) : "f"(lo), "f"(hi));
    return r;
}
__device__ __forceinline__ unsigned long long dup2(float v) {
    unsigned long long r;
    asm("mov.b64 %0, {%1,%1};" : "=l"(r) : "f"(v));
    return r;
}
__device__ __forceinline__ float2 unpack2(unsigned long long v) {
    float2 r;
    asm("mov.b64 {%0,%1}, %2;" : "=f"(r.x), "=f"(r.y) : "l"(v));
    return r;
}

// ---------------- cp.async helpers ------------------------------------------
__device__ __forceinline__ void cp_async16(void* smem_dst, const void* gsrc,
                                           unsigned src_bytes) {
    unsigned s = (unsigned)__cvta_generic_to_shared(smem_dst);
    asm volatile("cp.async.cg.shared.global [%0], [%1], 16, %2;"
                 :: "r"(s), "l"(gsrc), "r"(src_bytes));
}
__device__ __forceinline__ void cp_commit() {
    asm volatile("cp.async.commit_group;");
}
template<int N> __device__ __forceinline__ void cp_wait() {
    asm volatile("cp.async.wait_group %0;" :: "n"(N));
}

// ---------------- build x (embedding + evolutionary concat), TKB layout ----
__global__ __launch_bounds__(256) void build_x_kernel(
        const int* __restrict__ primary,
        const float* __restrict__ evo,
        const float* __restrict__ emb) {
    int t = blockIdx.x;
    for (int idx = threadIdx.x; idx < DIN*BATCH; idx += 256) {
        int d = idx >> 5;
        int b = idx & 31;
        float v;
        if (d < 32) {
            int p = primary[t*BATCH + b];
            v = emb[p*32 + d];
        } else {
            v = evo[((size_t)t*BATCH + b)*21 + (d - 32)];
        }
        g_xT[((size_t)t*DIN + d)*BATCH + b] = v;
    }
}

// ---------------- f32x2 SGEMM v4: cbuf[M][3200] = A_tkb @ B^T + bias --------
// A in TKB layout [T][K][32] (row m = t*32+b), B row-major [3200][K].
// A: 3-stage cp.async (one 16B op/thread/tile). B: register relay prefetched
// 2 tiles ahead (LDG.128 when K%4==0, scalar otherwise — K=53 rows are NOT
// 16B aligned), staged to smem via 4x STS.32. One __syncthreads per K-tile.
__global__ __launch_bounds__(256, 2) void gemm_tkb_kernel(
        const float* __restrict__ Bm, const float* __restrict__ bias,
        int K, int a_sel) {
    const float* __restrict__ A = a_sel ? g_h0T : g_xT;
    __shared__ float As[3][8*GP];
    __shared__ float Bs[2][8*GP];
    int m0 = blockIdx.x * 128;
    int n0 = blockIdx.y * 128;
    int tid = threadIdx.x;
    int tx = tid & 15, ty = tid >> 4;

    // A async-load mapping: thread -> (k row, 4 consecutive m)
    int ka  = tid >> 5;          // 0..7
    int ja  = tid & 31;          // m = 4*ja
    int tta = (m0 >> 5) + (ja >> 3);
    int bba = 4*(ja & 7);
    // B load mapping: thread -> (n row, 4 consecutive k)
    int nb = tid >> 1;           // 0..127
    int kq = (tid & 1) * 4;

    int nt = (K + 7) / 8;
    bool k_vec = ((K & 3) == 0);  // 16B-aligned B rows (uniform branch)

    auto issueA = [&](int kt, int buf) {
        int k = kt*8 + ka;
        int kc = (k < K) ? k : (K - 1);
        unsigned bytes = (k < K) ? 16u : 0u;
        cp_async16(&As[buf][ka*GP + 4*ja],
                   &A[((size_t)tta*K + kc)*BATCH + bba], bytes);
        cp_commit();
    };
    auto loadB = [&](int kt, float4& r) {
        int k = kt*8 + kq;
        const float* src = &Bm[(size_t)(n0 + nb)*K + k];
        if (k_vec && k + 3 < K) {
            r = *(const float4*)src;          // 16B aligned: K%4==0
        } else {
            r.x = (k+0 < K) ? src[0] : 0.f;
            r.y = (k+1 < K) ? src[1] : 0.f;
            r.z = (k+2 < K) ? src[2] : 0.f;
            r.w = (k+3 < K) ? src[3] : 0.f;
        }
    };

    unsigned long long acc2[4][8];
    #pragma unroll
    for (int i = 0; i < 4; i++)
        #pragma unroll
        for (int j = 0; j < 8; j++) acc2[i][j] = 0ULL;

    float4 breg[2];
    issueA(0, 0);
    if (nt > 1) issueA(1, 1);
    loadB(0, breg[0]);
    if (nt > 1) loadB(1, breg[1]);

    for (int kt = 0; kt < nt; kt++) {
        int cb = kt % 3;
        int bb = kt & 1;
        {   // stage current B tile into smem (conflict-free via GP pad)
            float4 bv = breg[bb];
            float* d = &Bs[bb][kq*GP + nb];
            d[0*GP] = bv.x; d[1*GP] = bv.y;
            d[2*GP] = bv.z; d[3*GP] = bv.w;
        }
        if (kt < nt - 1) cp_wait<1>(); else cp_wait<0>();  // A(kt) arrived
        __syncthreads();
        if (kt + 2 < nt) {
            issueA(kt + 2, (kt + 2) % 3);
            loadB(kt + 2, breg[bb]);       // slot just consumed by stageB
        }
        #pragma unroll
        for (int kk = 0; kk < 8; kk++) {
            float4 a0 = *(const float4*)&As[cb][kk*GP + ty*8];
            float4 a1 = *(const float4*)&As[cb][kk*GP + ty*8 + 4];
            float4 b0 = *(const float4*)&Bs[bb][kk*GP + tx*8];
            float4 b1 = *(const float4*)&Bs[bb][kk*GP + tx*8 + 4];
            unsigned long long ap[4];
            ap[0] = pack2(a0.x, a0.y); ap[1] = pack2(a0.z, a0.w);
            ap[2] = pack2(a1.x, a1.y); ap[3] = pack2(a1.z, a1.w);
            unsigned long long bd[8];
            bd[0] = dup2(b0.x); bd[1] = dup2(b0.y);
            bd[2] = dup2(b0.z); bd[3] = dup2(b0.w);
            bd[4] = dup2(b1.x); bd[5] = dup2(b1.y);
            bd[6] = dup2(b1.z); bd[7] = dup2(b1.w);
            #pragma unroll
            for (int i = 0; i < 4; i++)
                #pragma unroll
                for (int j = 0; j < 8; j++)
                    ffma2(acc2[i][j], ap[i], bd[j]);
        }
        __syncthreads();
    }

    #pragma unroll
    for (int j = 0; j < 8; j++) {
        int col = n0 + tx*8 + j;
        float bv = __ldg(&bias[col]);
        #pragma unroll
        for (int i = 0; i < 4; i++) {
            float2 v = unpack2(acc2[i][j]);
            int row = m0 + ty*8 + 2*i;
            g_cbuf[(size_t)row*G4 + col]       = v.x + bv;
            g_cbuf[(size_t)(row+1)*G4 + col]   = v.y + bv;
        }
    }
}

// ---------------- transpose g_cbuf [t*32+b][3200] -> xgT [t][3200][32] ------
__global__ void transpose_kernel(int dst_sel) {
    float* __restrict__ dst = dst_sel ? g_xgTb : g_xgTf;
    __shared__ float sm[32][33];
    int t  = blockIdx.x;
    int n0 = blockIdx.y * 32;
    int x = threadIdx.x, y = threadIdx.y;   // 32 x 8
    #pragma unroll
    for (int i = 0; i < 4; i++) {
        int b = y + i*8;
        sm[b][x] = g_cbuf[((size_t)t*BATCH + b)*G4 + n0 + x];
    }
    __syncthreads();
    #pragma unroll
    for (int i = 0; i < 4; i++) {
        int n = y + i*8;
        dst[((size_t)t*G4 + n0 + n)*BATCH + x] = sm[x][n];
    }
}

// ---------------- per-direction device-wide barrier (generation based) ------
__device__ __forceinline__ void grid_barrier_dir(int dir) {
    __syncthreads();
    if (threadIdx.x == 0) {
        unsigned my = g_bar_gen2[dir];
        __threadfence();
        if (atomicAdd(&g_bar_cnt2[dir], 1) == NB_DIR - 1) {
            g_bar_cnt2[dir] = 0;
            __threadfence();
            g_bar_gen2[dir] = my + 1;
        } else {
            while (g_bar_gen2[dir] == my) { }
            __threadfence();
        }
    }
    __syncthreads();
}

// ---------------- persistent bidirectional LSTM layer (v3) ------------------
// 148 blocks: 74 per direction (independent barriers). Block owns nh (10-11)
// hidden units = 4*nh gate rows; each warp sweeps up to 6 rows, ALL of whose
// Whh rows are cached in smem (no L2 streaming in the hot loop). Previous h
// is staged [b][k] through a 3-slot smem ring of k=160 chunks via cp.async.cg,
// overlapped with the packed fma.rn.f32x2 accumulation of earlier chunks.
__global__ __launch_bounds__(256, 1) void lstm_kernel(
        const float* __restrict__ Whhf, const float* __restrict__ Whhb,
        int layer) {
    extern __shared__ float smem[];
    float* ring = smem;                       // [3][32][RCH] h chunks, [b][k]
    float* wsm  = ring + 3*RSLOT;             // [44][800] cached Whh rows
    float* pre  = wsm + 44*HID;               // [44*32] gate pre-activations
    float* csm  = pre + 44*BATCH;             // [11*32] cell state
    float* hout = layer ? g_h1T : g_h0T;

    int bid = blockIdx.x;
    int dir = (bid >= NB_DIR) ? 1 : 0;
    int lb  = dir ? bid - NB_DIR : bid;       // 0..73
    int nh, h0;
    if (lb < 60) { nh = 11; h0 = lb*11; }
    else         { nh = 10; h0 = 660 + (lb-60)*10; }
    const float* __restrict__ xgT = dir ? g_xgTb : g_xgTf;
    const float* __restrict__ Whh = dir ? Whhb : Whhf;

    int tid = threadIdx.x;
    int lane = tid & 31, w = tid >> 5;
    int nrows = nh * 4;                       // 40 or 44

    int grows[6], wrow[6];
    bool valid[6];
    #pragma unroll
    for (int s = 0; s < 6; s++) {
        int lr = w + 8*s;
        bool v = lr < nrows;
        int lru = v ? lr : 0;
        grows[s] = (lru & 3)*HID + h0 + (lru >> 2);
        wrow[s]  = lru;
        valid[s] = v;
    }

    // preload ALL gate-row weights into smem (one-time, per layer)
    for (int lr = 0; lr < nrows; lr++) {
        int g = (lr & 3)*HID + h0 + (lr >> 2);
        const float* src = Whh + (size_t)g*HID;
        for (int k = tid; k < HID; k += 256) wsm[lr*HID + k] = src[k];
    }

    // zero-init c (smem) and own slots of h parity-0 buffer [b][k]
    for (int i = tid; i < nh*BATCH; i += 256) {
        csm[i] = 0.f;
        int hl = i >> 5, b = i & 31;
        g_hstate[(size_t)(dir*2 + 0)*HID*BATCH + b*HID + (h0 + hl)] = 0.f;
    }
    grid_barrier_dir(dir);

    for (int t = 0; t < T_SEQ; t++) {
        int te = dir ? (T_SEQ - 1 - t) : t;
        int p = t & 1;
        const float* hsg = &g_hstate[(size_t)(dir*2 + p)*HID*BATCH];

        auto stage = [&](int c) {             // stage h chunk c into ring slot c%3
            float* dst = ring + (c % 3)*RSLOT;
            #pragma unroll
            for (int j = 0; j < 5; j++) {
                int q  = tid + j*256;         // 0..1279
                int b  = q / 40;
                int kk = (q - b*40)*4;
                cp_async16(&dst[b*RCH + kk], &hsg[b*HID + c*KCH + kk], 16u);
            }
            cp_commit();
        };

        // init accumulators with xg (DRAM LDGs overlap staging below)
        unsigned long long a0[6], a1[6];
        #pragma unroll
        for (int s = 0; s < 6; s++) {
            float xg = xgT[((size_t)te*G4 + grows[s])*BATCH + lane];
            a0[s] = pack2(xg, 0.f);
            a1[s] = 0ULL;
        }

        stage(0); stage(1); stage(2);

        // phase A: consume chunks through the ring, packed f32x2, 6 rows/warp
        #pragma unroll
        for (int c = 0; c < 5; c++) {
            if (c < 3) cp_wait<2>();
            else if (c == 3) cp_wait<1>();
            else cp_wait<0>();
            __syncthreads();
            const float* hrow = ring + (c % 3)*RSLOT + lane*RCH;
            int kbase = c*KCH;
            #pragma unroll 4
            for (int kl = 0; kl < KCH; kl += 4) {
                ulonglong2 hv = *(const ulonglong2*)(hrow + kl);
                #pragma unroll
                for (int s = 0; s < 6; s++) {
                    ulonglong2 wv = *(const ulonglong2*)&wsm[wrow[s]*HID + kbase + kl];
                    ffma2(a0[s], hv.x, wv.x);
                    ffma2(a1[s], hv.y, wv.y);
                }
            }
            if (c < 2) {                      // reuse freed slot for chunk c+3
                __syncthreads();
                stage(c + 3);
            }
        }
        #pragma unroll
        for (int s = 0; s < 6; s++) {
            if (valid[s]) {
                float2 x = unpack2(a0[s]);
                float2 y = unpack2(a1[s]);
                pre[(w + 8*s)*BATCH + lane] = (x.x + x.y) + (y.x + y.y);
            }
        }
        __syncthreads();

        // phase B: gate nonlinearity + state update
        for (int i = tid; i < nh*BATCH; i += 256) {
            int hl = i >> 5, b = i & 31;
            float iv = pre[(hl*4+0)*BATCH + b];
            float fv = pre[(hl*4+1)*BATCH + b];
            float gv = pre[(hl*4+2)*BATCH + b];
            float ov = pre[(hl*4+3)*BATCH + b];
            float si = 1.f/(1.f + expf(-iv));
            float sf = 1.f/(1.f + expf(-fv));
            float so = 1.f/(1.f + expf(-ov));
            float c  = sf*csm[i] + si*tanhf(gv);
            float hv = so*tanhf(c);
            csm[i] = c;
            int hi = h0 + hl;
            g_hstate[(size_t)(dir*2 + (1-p))*HID*BATCH + b*HID + hi] = hv;
            hout[((size_t)te*L1K + dir*HID + hi)*BATCH + b] = hv;
        }
        grid_barrier_dir(dir);
    }
}

// ---------------- FC + softmax-free angularization -> dihedrals -------------
__global__ __launch_bounds__(256) void fc_dih_kernel(
        const float* __restrict__ fcW, const float* __restrict__ fcb,
        const float* __restrict__ alphabet) {
    __shared__ float chunk[256*BATCH];   // 32KB feature chunk [k][b]
    __shared__ float lsm[NA*BATCH];
    __shared__ float sn[NA*3], cs[NA*3];
    int t = blockIdx.x;
    int tid = threadIdx.x;
    int lane = tid & 31, w = tid >> 5;

    float acc[8];
    #pragma unroll
    for (int i = 0; i < 8; i++) acc[i] = 0.f;

    for (int c0 = 0; c0 < RNNOUT; c0 += 256) {
        int clen = RNNOUT - c0; if (clen > 256) clen = 256;
        for (int idx = tid; idx < clen*BATCH; idx += 256) {
            int k = idx >> 5, b = idx & 31;
            int f = c0 + k;
            chunk[idx] = (f < L1K)
                ? g_h1T[((size_t)t*L1K + f)*BATCH + b]
                : g_xT [((size_t)t*DIN + (f - L1K))*BATCH + b];
        }
        __syncthreads();
        #pragma unroll
        for (int i = 0; i < 8; i++) {
            int a = w*8 + i;
            if (a < NA) {
                const float* wr = fcW + (size_t)a*RNNOUT + c0;
                float s = acc[i];
                #pragma unroll 4
                for (int k = 0; k < clen; k++)
                    s = fmaf(__ldg(wr + k), chunk[k*BATCH + lane], s);
                acc[i] = s;
            }
        }
        __syncthreads();
    }
    #pragma unroll
    for (int i = 0; i < 8; i++) {
        int a = w*8 + i;
        if (a < NA) lsm[a*BATCH + lane] = acc[i] + fcb[a];
    }
    for (int i = tid; i < NA*3; i += 256) {
        float v = alphabet[i];
        sn[i] = sinf(v); cs[i] = cosf(v);
    }
    __syncthreads();
    if (tid < 96) {
        int b = tid & 31, j = tid >> 5;
        float ss = 0.f, cc = 0.f;
        for (int a = 0; a < NA; a++) {
            float e = expf(lsm[a*BATCH + b]);   // softmax Z cancels in atan2
            ss = fmaf(e, sn[a*3 + j], ss);
            cc = fmaf(e, cs[a*3 + j], cc);
        }
        g_dih[((size_t)t*BATCH + b)*3 + j] = atan2f(ss, cc);
    }
}

// ---------------- dihedral -> points -> NeRF coordinate extension -----------
__global__ void geometry_kernel(float* __restrict__ out) {
    int b = threadIdx.x;   // 0..31, one lane per batch element
    const float PI = 3.14159265358979323846f;
    float BL[3] = {145.801f, 152.326f, 132.868f};
    float BA[3] = {2.124f, 1.941f, 2.028f};
    float rct[3], rst[3];
    #pragma unroll
    for (int j = 0; j < 3; j++) {
        rct[j] = BL[j]*cosf(PI - BA[j]);
        rst[j] = BL[j]*sinf(PI - BA[j]);
    }
    float ax = -sqrtf(0.5f), ay = sqrtf(1.5f), az = 0.f;
    float bx = -sqrtf(2.0f), by = 0.f,        bz = 0.f;
    float cx = 0.f, cy = 0.f, cz = 0.f;

    for (int i = 0; i < 3*T_SEQ; i++) {
        int t = i / 3, j = i - 3*t;
        float d  = g_dih[((size_t)t*BATCH + b)*3 + j];
        float p0 = rct[j];
        float p1 = cosf(d)*rst[j];
        float p2 = sinf(d)*rst[j];

        float ux = cx-bx, uy = cy-by, uz = cz-bz;
        float inv = 1.f/sqrtf(ux*ux + uy*uy + uz*uz + 1e-12f);
        float bcx = ux*inv, bcy = uy*inv, bcz = uz*inv;

        float vx = bx-ax, vy = by-ay, vz = bz-az;
        float nx0 = vy*bcz - vz*bcy;
        float ny0 = vz*bcx - vx*bcz;
        float nz0 = vx*bcy - vy*bcx;
        float inv2 = 1.f/sqrtf(nx0*nx0 + ny0*ny0 + nz0*nz0 + 1e-12f);
        float nx = nx0*inv2, ny = ny0*inv2, nz = nz0*inv2;

        float mx = ny*bcz - nz*bcy;
        float my = nz*bcx - nx*bcz;
        float mz = nx*bcy - ny*bcx;

        float ox = cx + p0*bcx + p1*mx + p2*nx;
        float oy = cy + p0*bcy + p1*my + p2*ny;
        float oz = cz + p0*bcz + p1*mz + p2*nz;

        size_t o = ((size_t)i*BATCH + b)*3;
        out[o+0] = ox; out[o+1] = oy; out[o+2] = oz;

        ax = bx; ay = by; az = bz;
        bx = cx; by = cy; bz = cz;
        cx = ox; cy = oy; cz = oz;
    }
}

// ---------------- launch ----------------------------------------------------
extern "C" void kernel_launch(void* const* d_in, const int* in_sizes, int n_in,
                              void* d_out, int out_size) {
    const int*   primary = (const int*)  d_in[0];
    const float* evo     = (const float*)d_in[1];
    // d_in[2] = seq_length (fixed 700, ignored)
    const float* emb     = (const float*)d_in[3];
    const float* Wih0f   = (const float*)d_in[4];
    const float* Whh0f   = (const float*)d_in[5];
    const float* b0f     = (const float*)d_in[6];
    const float* Wih0b   = (const float*)d_in[7];
    const float* Whh0b   = (const float*)d_in[8];
    const float* b0b     = (const float*)d_in[9];
    const float* Wih1f   = (const float*)d_in[10];
    const float* Whh1f   = (const float*)d_in[11];
    const float* b1f     = (const float*)d_in[12];
    const float* Wih1b   = (const float*)d_in[13];
    const float* Whh1b   = (const float*)d_in[14];
    const float* b1b     = (const float*)d_in[15];
    const float* fcW     = (const float*)d_in[16];
    const float* fcb     = (const float*)d_in[17];
    const float* alphabet= (const float*)d_in[18];
    float* out = (float*)d_out;

    cudaFuncSetAttribute(lstm_kernel,
                         cudaFuncAttributeMaxDynamicSharedMemorySize, LSTM_SMEM);

    dim3 ggrid(175, 25);           // 22400/128, 3200/128
    dim3 tgrid(T_SEQ, 100);        // 3200/32
    dim3 tblk(32, 8);

    build_x_kernel<<<T_SEQ, 256>>>(primary, evo, emb);

    // layer 0 input projections
    gemm_tkb_kernel<<<ggrid, 256>>>(Wih0f, b0f, DIN, 0);
    transpose_kernel<<<tgrid, tblk>>>(0);
    gemm_tkb_kernel<<<ggrid, 256>>>(Wih0b, b0b, DIN, 0);
    transpose_kernel<<<tgrid, tblk>>>(1);
    lstm_kernel<<<NB_LSTM, 256, LSTM_SMEM>>>(Whh0f, Whh0b, 0);

    // layer 1 input projections
    gemm_tkb_kernel<<<ggrid, 256>>>(Wih1f, b1f, L1K, 1);
    transpose_kernel<<<tgrid, tblk>>>(0);
    gemm_tkb_kernel<<<ggrid, 256>>>(Wih1b, b1b, L1K, 1);
    transpose_kernel<<<tgrid, tblk>>>(1);
    lstm_kernel<<<NB_LSTM, 256, LSTM_SMEM>>>(Whh1f, Whh1b, 1);

    fc_dih_kernel<<<T_SEQ, 256>>>(fcW, fcb, alphabet);
    geometry_kernel<<<1, 32>>>(out);
}